// round 1
// baseline (speedup 1.0000x reference)
#include <cuda_runtime.h>
#include <cuda_bf16.h>
#include <math_constants.h>

// Problem constants
#define T_TOK   2048
#define D_MODEL 1024
#define HIDDEN  4096
#define N_EXP   8
// TOP_K = 2

// ---------------- device scratch (allocation-free) ----------------
__device__ int   g_count[N_EXP];                    // tokens routed to each expert
__device__ int   g_tok[N_EXP * T_TOK];              // packed token*2 + slot
__device__ float g_wt [N_EXP * T_TOK];              // combine weight for that slot
__device__ float g_probs[T_TOK * N_EXP];            // full softmax probs (for l_bal)
__device__ float g_scratch[(size_t)T_TOK * 2 * HIDDEN]; // 64 MB per-(token,slot) partials

// ---------------- kernel 0: zero counters ----------------
__global__ void init_kernel() {
    if (threadIdx.x < N_EXP) g_count[threadIdx.x] = 0;
}

// ---------------- kernel 1: router ----------------
// one block per token, 256 threads = 8 warps; warp e computes logit e.
__global__ __launch_bounds__(256) void router_kernel(
    const float* __restrict__ x, const float* __restrict__ rw)
{
    int t    = blockIdx.x;
    int warp = threadIdx.x >> 5;
    int lane = threadIdx.x & 31;

    const float4* xv = (const float4*)(x + (size_t)t * D_MODEL);
    const float4* wv = (const float4*)(rw + (size_t)warp * D_MODEL);
    float s = 0.f;
    #pragma unroll
    for (int i = 0; i < 8; i++) {          // 8 * 32 lanes * 4 = 1024
        float4 a = xv[lane + i * 32];
        float4 b = wv[lane + i * 32];
        s += a.x * b.x + a.y * b.y + a.z * b.z + a.w * b.w;
    }
    #pragma unroll
    for (int o = 16; o > 0; o >>= 1) s += __shfl_xor_sync(0xffffffffu, s, o);

    __shared__ float logits[N_EXP];
    if (lane == 0) logits[warp] = s;
    __syncthreads();

    if (threadIdx.x == 0) {
        // top-2 (strict > keeps lowest index on ties, matching jax top_k)
        int e0 = 0; float v0 = logits[0];
        #pragma unroll
        for (int e = 1; e < N_EXP; e++) if (logits[e] > v0) { v0 = logits[e]; e0 = e; }
        int e1 = -1; float v1 = -CUDART_INF_F;
        #pragma unroll
        for (int e = 0; e < N_EXP; e++) if (e != e0 && logits[e] > v1) { v1 = logits[e]; e1 = e; }

        // softmax over the two selected logits (v0 >= v1)
        float ex1 = expf(v1 - v0);
        float inv = 1.0f / (1.0f + ex1);
        float c0 = inv, c1 = ex1 * inv;

        int p0 = atomicAdd(&g_count[e0], 1);
        g_tok[e0 * T_TOK + p0] = t * 2 + 0;
        g_wt [e0 * T_TOK + p0] = c0;
        int p1 = atomicAdd(&g_count[e1], 1);
        g_tok[e1 * T_TOK + p1] = t * 2 + 1;
        g_wt [e1 * T_TOK + p1] = c1;

        // full softmax for P (l_bal)
        float mx = v0;   // v0 is the max
        float pe[N_EXP], se = 0.f;
        #pragma unroll
        for (int e = 0; e < N_EXP; e++) { pe[e] = expf(logits[e] - mx); se += pe[e]; }
        float invs = 1.0f / se;
        #pragma unroll
        for (int e = 0; e < N_EXP; e++) g_probs[t * N_EXP + e] = pe[e] * invs;
    }
}

// ---------------- kernel 2: grouped expert GEMM ----------------
// C[m, n] = sum_k Xgather[m, k] * W1[e][n, k]   then scale by weight, +bias,
// scatter into g_scratch[(token,slot)].
// Tile: BM=128, BN=128, BK=8, 256 threads, 8x8 micro-tile per thread.
#define BM 128
#define BN 128
#define BK 8

__global__ __launch_bounds__(256) void moe_gemm_kernel(
    const float* __restrict__ x,
    const float* __restrict__ w1,
    const float* __restrict__ b1)
{
    const int e     = blockIdx.z;
    const int mtile = blockIdx.y;
    const int ntile = blockIdx.x;
    const int cnt   = g_count[e];
    const int m0    = mtile * BM;
    if (m0 >= cnt) return;

    __shared__ float As[BK][BM];
    __shared__ float Bs[BK][BN];

    const int tid = threadIdx.x;
    const int tm  = (tid >> 4) << 3;     // 0..120 step 8
    const int tn  = (tid & 15) << 3;     // 0..120 step 8

    // load mapping: 1024 floats per tile per operand, 4 per thread (float4)
    const int ia = tid & 127;            // row within A tile
    const int ka = (tid >> 7) << 2;      // k offset (0 or 4)
    const int nb = tid & 127;            // col within B tile
    const int kb = (tid >> 7) << 2;

    const float* aptr = nullptr;
    {
        int row = m0 + ia;
        if (row < cnt) {
            int packed = g_tok[e * T_TOK + row];
            aptr = x + (size_t)(packed >> 1) * D_MODEL;
        }
    }
    const float* bptr = w1 + ((size_t)e * HIDDEN + (size_t)ntile * BN + nb) * D_MODEL;

    float acc[8][8];
    #pragma unroll
    for (int i = 0; i < 8; i++)
        #pragma unroll
        for (int j = 0; j < 8; j++) acc[i][j] = 0.f;

    for (int k0 = 0; k0 < D_MODEL; k0 += BK) {
        float4 av = aptr ? *(const float4*)(aptr + k0 + ka) : make_float4(0.f, 0.f, 0.f, 0.f);
        As[ka + 0][ia] = av.x; As[ka + 1][ia] = av.y;
        As[ka + 2][ia] = av.z; As[ka + 3][ia] = av.w;

        float4 bv = *(const float4*)(bptr + k0 + kb);
        Bs[kb + 0][nb] = bv.x; Bs[kb + 1][nb] = bv.y;
        Bs[kb + 2][nb] = bv.z; Bs[kb + 3][nb] = bv.w;
        __syncthreads();

        #pragma unroll
        for (int k = 0; k < BK; k++) {
            float ra[8], rb[8];
            #pragma unroll
            for (int i = 0; i < 8; i++) ra[i] = As[k][tm + i];
            #pragma unroll
            for (int j = 0; j < 8; j++) rb[j] = Bs[k][tn + j];
            #pragma unroll
            for (int i = 0; i < 8; i++)
                #pragma unroll
                for (int j = 0; j < 8; j++)
                    acc[i][j] += ra[i] * rb[j];
        }
        __syncthreads();
    }

    // epilogue: scale + bias, scatter to (token,slot) scratch rows (no atomics)
    const int nbase = ntile * BN + tn;
    float bias[8];
    #pragma unroll
    for (int j = 0; j < 8; j++) bias[j] = b1[(size_t)e * HIDDEN + nbase + j];

    #pragma unroll
    for (int i = 0; i < 8; i++) {
        int r = m0 + tm + i;
        if (r >= cnt) continue;
        int packed = g_tok[e * T_TOK + r];
        float w    = g_wt [e * T_TOK + r];
        float* dst = g_scratch + (size_t)packed * HIDDEN + nbase;
        float4 o0, o1;
        o0.x = w * (acc[i][0] + bias[0]);
        o0.y = w * (acc[i][1] + bias[1]);
        o0.z = w * (acc[i][2] + bias[2]);
        o0.w = w * (acc[i][3] + bias[3]);
        o1.x = w * (acc[i][4] + bias[4]);
        o1.y = w * (acc[i][5] + bias[5]);
        o1.z = w * (acc[i][6] + bias[6]);
        o1.w = w * (acc[i][7] + bias[7]);
        *(float4*)(dst + 0) = o0;
        *(float4*)(dst + 4) = o1;
    }
}

// ---------------- kernel 3: combine two slots ----------------
__global__ __launch_bounds__(256) void combine_kernel(float* __restrict__ out)
{
    size_t i = ((size_t)blockIdx.x * blockDim.x + threadIdx.x) * 4;  // float4 granularity
    // i over T_TOK*HIDDEN
    size_t t = i >> 12;          // / HIDDEN
    size_t h = i & (HIDDEN - 1);
    const float4 a = *(const float4*)(g_scratch + ((t << 1) + 0) * HIDDEN + h);
    const float4 b = *(const float4*)(g_scratch + ((t << 1) + 1) * HIDDEN + h);
    float4 o;
    o.x = a.x + b.x; o.y = a.y + b.y; o.z = a.z + b.z; o.w = a.w + b.w;
    *(float4*)(out + i) = o;
}

// ---------------- kernel 4: l_bal scalar ----------------
__global__ __launch_bounds__(256) void lbal_kernel(float* __restrict__ out)
{
    int warp = threadIdx.x >> 5;   // 8 warps, one per expert
    int lane = threadIdx.x & 31;
    float s = 0.f;
    for (int t = lane; t < T_TOK; t += 32) s += g_probs[t * N_EXP + warp];
    #pragma unroll
    for (int o = 16; o > 0; o >>= 1) s += __shfl_xor_sync(0xffffffffu, s, o);
    __shared__ float P[N_EXP];
    if (lane == 0) P[warp] = s;
    __syncthreads();
    if (threadIdx.x == 0) {
        float l = 0.f;
        #pragma unroll
        for (int e = 0; e < N_EXP; e++) {
            float f = (float)g_count[e] / (float)T_TOK;
            l += f * (P[e] / (float)T_TOK);
        }
        out[(size_t)T_TOK * HIDDEN] = (float)N_EXP * l;
    }
}

// ---------------- launch ----------------
extern "C" void kernel_launch(void* const* d_in, const int* in_sizes, int n_in,
                              void* d_out, int out_size)
{
    const float* x  = (const float*)d_in[0];   // [1,2048,1024]
    const float* rw = (const float*)d_in[1];   // [8,1024]
    const float* w1 = (const float*)d_in[2];   // [8,4096,1024]
    const float* b1 = (const float*)d_in[3];   // [8,4096]
    float* out = (float*)d_out;

    init_kernel<<<1, 32>>>();
    router_kernel<<<T_TOK, 256>>>(x, rw);

    dim3 gemm_grid(HIDDEN / BN, T_TOK / BM, N_EXP);   // (32, 16, 8); most m-tiles exit early
    moe_gemm_kernel<<<gemm_grid, 256>>>(x, w1, b1);

    size_t total = (size_t)T_TOK * HIDDEN;
    combine_kernel<<<(unsigned)(total / 4 / 256), 256>>>(out);

    if ((size_t)out_size > total) {
        lbal_kernel<<<1, 256>>>(out);
    }
}

// round 4
// speedup vs baseline: 3.5867x; 3.5867x over previous
#include <cuda_runtime.h>
#include <cuda_bf16.h>
#include <math_constants.h>
#include <cstdint>

// Problem constants
#define T_TOK   2048
#define D_MODEL 1024
#define HIDDEN  4096
#define N_EXP   8
// TOP_K = 2

// GEMM tiling
#define BM 128
#define BN 128
#define KC 32                    // k-chunk (fp32 elements)
#define NCHUNK (D_MODEL / KC)    // 32
#define STRIDE 36                // padded smem row stride (floats): (4r+c)%32 conflict-free
#define TILE_FLOATS (128 * STRIDE)   // 4608 floats = 18KB per operand buffer

// ---------------- device scratch (allocation-free) ----------------
__device__ int   g_count[N_EXP];
__device__ int   g_tok[N_EXP * T_TOK];              // packed token*2 + slot
__device__ float g_wt [N_EXP * T_TOK];
__device__ float g_probs[T_TOK * N_EXP];
__device__ float g_scratch[(size_t)T_TOK * 2 * HIDDEN]; // 64 MB per-(token,slot) partials

// ---------------- helpers ----------------
__device__ __forceinline__ uint32_t smem_u32(const void* p) {
    uint32_t a;
    asm("{ .reg .u64 t; cvta.to.shared.u64 t, %1; cvt.u32.u64 %0, t; }" : "=r"(a) : "l"(p));
    return a;
}

__device__ __forceinline__ void cp16(uint32_t dst, const void* src, int sz) {
    asm volatile("cp.async.cg.shared.global [%0], [%1], 16, %2;"
                 :: "r"(dst), "l"(src), "r"(sz) : "memory");
}

__device__ __forceinline__ uint32_t cvt_tf32(float v) {
    uint32_t u;
    asm("cvt.rna.tf32.f32 %0, %1;" : "=r"(u) : "f"(v));
    return u;
}

__device__ __forceinline__ void mma_tf32(float* d, const uint32_t* a, const uint32_t* b) {
    asm volatile(
        "mma.sync.aligned.m16n8k8.row.col.f32.tf32.tf32.f32 "
        "{%0,%1,%2,%3}, {%4,%5,%6,%7}, {%8,%9}, {%0,%1,%2,%3};"
        : "+f"(d[0]), "+f"(d[1]), "+f"(d[2]), "+f"(d[3])
        : "r"(a[0]), "r"(a[1]), "r"(a[2]), "r"(a[3]),
          "r"(b[0]), "r"(b[1]));
}

// ---------------- kernel 0: zero counters ----------------
__global__ void init_kernel() {
    if (threadIdx.x < N_EXP) g_count[threadIdx.x] = 0;
}

// ---------------- kernel 1: router ----------------
__global__ __launch_bounds__(256) void router_kernel(
    const float* __restrict__ x, const float* __restrict__ rw)
{
    int t    = blockIdx.x;
    int warp = threadIdx.x >> 5;
    int lane = threadIdx.x & 31;

    const float4* xv = (const float4*)(x + (size_t)t * D_MODEL);
    const float4* wv = (const float4*)(rw + (size_t)warp * D_MODEL);
    float s = 0.f;
    #pragma unroll
    for (int i = 0; i < 8; i++) {
        float4 a = xv[lane + i * 32];
        float4 b = wv[lane + i * 32];
        s += a.x * b.x + a.y * b.y + a.z * b.z + a.w * b.w;
    }
    #pragma unroll
    for (int o = 16; o > 0; o >>= 1) s += __shfl_xor_sync(0xffffffffu, s, o);

    __shared__ float logits[N_EXP];
    if (lane == 0) logits[warp] = s;
    __syncthreads();

    if (threadIdx.x == 0) {
        int e0 = 0; float v0 = logits[0];
        #pragma unroll
        for (int e = 1; e < N_EXP; e++) if (logits[e] > v0) { v0 = logits[e]; e0 = e; }
        int e1 = -1; float v1 = -CUDART_INF_F;
        #pragma unroll
        for (int e = 0; e < N_EXP; e++) if (e != e0 && logits[e] > v1) { v1 = logits[e]; e1 = e; }

        float ex1 = expf(v1 - v0);
        float inv = 1.0f / (1.0f + ex1);
        float c0 = inv, c1 = ex1 * inv;

        int p0 = atomicAdd(&g_count[e0], 1);
        g_tok[e0 * T_TOK + p0] = t * 2 + 0;
        g_wt [e0 * T_TOK + p0] = c0;
        int p1 = atomicAdd(&g_count[e1], 1);
        g_tok[e1 * T_TOK + p1] = t * 2 + 1;
        g_wt [e1 * T_TOK + p1] = c1;

        float mx = v0;
        float pe[N_EXP], se = 0.f;
        #pragma unroll
        for (int e = 0; e < N_EXP; e++) { pe[e] = expf(logits[e] - mx); se += pe[e]; }
        float invs = 1.0f / se;
        #pragma unroll
        for (int e = 0; e < N_EXP; e++) g_probs[t * N_EXP + e] = pe[e] * invs;
    }
}

// ---------------- kernel 2: mma.sync tf32 grouped expert GEMM ----------------
// CTA 128x128, 4 warps (2x2), warp tile 64x64 via m16n8k8 tf32 mma.sync.
// A rows gathered from x via router lists. cp.async double-buffered staging.
__global__ void __launch_bounds__(128, 1) moe_gemm_mma(
    const float* __restrict__ x,
    const float* __restrict__ w1,
    const float* __restrict__ b1)
{
    const int e   = blockIdx.z;
    const int cnt = g_count[e];
    const int m0  = blockIdx.x * BM;
    if (m0 >= cnt) return;
    const int n0  = blockIdx.y * BN;

    extern __shared__ float dynsmem[];
    float* As = dynsmem;                       // [2][128][STRIDE]
    float* Bs = dynsmem + 2 * TILE_FLOATS;     // [2][128][STRIDE]

    __shared__ int   s_tok[BM];
    __shared__ float s_w[BM];
    __shared__ float s_bias[BN];

    const int tid  = threadIdx.x;
    const int wid  = tid >> 5;
    const int lid  = tid & 31;
    const int wm   = (wid >> 1) * 64;   // warp row base within tile
    const int wn   = (wid & 1) * 64;    // warp col base within tile
    const int lr   = lid >> 2;          // lane row (0..7)
    const int lc   = lid & 3;           // lane col (0..3)

    // per-row metadata
    {
        int r = m0 + tid;
        if (r < cnt) { s_tok[tid] = g_tok[e * T_TOK + r]; s_w[tid] = g_wt[e * T_TOK + r]; }
        else         { s_tok[tid] = -1;                   s_w[tid] = 0.f; }
        s_bias[tid] = b1[(size_t)e * HIDDEN + n0 + tid];
    }
    __syncthreads();

    const float* w1base = w1 + ((size_t)e * HIDDEN + n0) * D_MODEL;
    const uint32_t uA = smem_u32(As);
    const uint32_t uB = smem_u32(Bs);

    // ---- staging lambda: chunk k0 -> buffer buf ----
    auto stage = [&](int buf, int k0) {
        uint32_t ab = uA + (uint32_t)buf * TILE_FLOATS * 4;
        uint32_t bb = uB + (uint32_t)buf * TILE_FLOATS * 4;
        #pragma unroll
        for (int i = 0; i < 8; i++) {
            int idx = i * 128 + tid;
            int r   = idx >> 3;
            int cq  = idx & 7;
            int pk  = s_tok[r];
            int tok = pk >= 0 ? (pk >> 1) : 0;
            const float* src = x + (size_t)tok * D_MODEL + k0 + cq * 4;
            cp16(ab + (uint32_t)(r * STRIDE + cq * 4) * 4, src, pk >= 0 ? 16 : 0);
        }
        #pragma unroll
        for (int i = 0; i < 8; i++) {
            int idx = i * 128 + tid;
            int r   = idx >> 3;
            int cq  = idx & 7;
            const float* src = w1base + (size_t)r * D_MODEL + k0 + cq * 4;
            cp16(bb + (uint32_t)(r * STRIDE + cq * 4) * 4, src, 16);
        }
        asm volatile("cp.async.commit_group;" ::: "memory");
    };

    float acc[4][8][4];
    #pragma unroll
    for (int mt = 0; mt < 4; mt++)
        #pragma unroll
        for (int nt = 0; nt < 8; nt++)
            #pragma unroll
            for (int q = 0; q < 4; q++) acc[mt][nt][q] = 0.f;

    stage(0, 0);

    for (int c = 0; c < NCHUNK; ++c) {
        if (c + 1 < NCHUNK) stage((c + 1) & 1, (c + 1) * KC);
        else asm volatile("cp.async.commit_group;" ::: "memory");  // empty group
        asm volatile("cp.async.wait_group 1;" ::: "memory");
        __syncthreads();

        const float* Ab = As + (c & 1) * TILE_FLOATS;
        const float* Bb = Bs + (c & 1) * TILE_FLOATS;

        #pragma unroll
        for (int s = 0; s < 4; s++) {
            const int c0 = s * 8;
            uint32_t af[4][4];
            #pragma unroll
            for (int mt = 0; mt < 4; mt++) {
                const float* p = Ab + (wm + mt * 16 + lr) * STRIDE + c0 + lc;
                af[mt][0] = cvt_tf32(p[0]);
                af[mt][1] = cvt_tf32(p[8 * STRIDE]);
                af[mt][2] = cvt_tf32(p[4]);
                af[mt][3] = cvt_tf32(p[8 * STRIDE + 4]);
            }
            uint32_t bf2[8][2];
            #pragma unroll
            for (int nt = 0; nt < 8; nt++) {
                const float* p = Bb + (wn + nt * 8 + lr) * STRIDE + c0 + lc;
                bf2[nt][0] = cvt_tf32(p[0]);
                bf2[nt][1] = cvt_tf32(p[4]);
            }
            #pragma unroll
            for (int mt = 0; mt < 4; mt++)
                #pragma unroll
                for (int nt = 0; nt < 8; nt++)
                    mma_tf32(acc[mt][nt], af[mt], bf2[nt]);
        }
        __syncthreads();
    }

    // ---- epilogue: scale + bias, scatter to per-(token,slot) scratch ----
    #pragma unroll
    for (int mt = 0; mt < 4; mt++) {
        int r_lo = wm + mt * 16 + lr;     // local row for d0/d1
        int r_hi = r_lo + 8;              // local row for d2/d3
        bool ok0 = (m0 + r_lo) < cnt;
        bool ok1 = (m0 + r_hi) < cnt;
        if (ok0) {
            int   pk = s_tok[r_lo];
            float wt = s_w[r_lo];
            float* dst = g_scratch + (size_t)pk * HIDDEN + n0;
            #pragma unroll
            for (int nt = 0; nt < 8; nt++) {
                int col = wn + nt * 8 + lc * 2;
                float2 v;
                v.x = wt * (acc[mt][nt][0] + s_bias[col]);
                v.y = wt * (acc[mt][nt][1] + s_bias[col + 1]);
                *(float2*)(dst + col) = v;
            }
        }
        if (ok1) {
            int   pk = s_tok[r_hi];
            float wt = s_w[r_hi];
            float* dst = g_scratch + (size_t)pk * HIDDEN + n0;
            #pragma unroll
            for (int nt = 0; nt < 8; nt++) {
                int col = wn + nt * 8 + lc * 2;
                float2 v;
                v.x = wt * (acc[mt][nt][2] + s_bias[col]);
                v.y = wt * (acc[mt][nt][3] + s_bias[col + 1]);
                *(float2*)(dst + col) = v;
            }
        }
    }
}

// ---------------- kernel 3: combine two slots ----------------
__global__ __launch_bounds__(256) void combine_kernel(float* __restrict__ out)
{
    size_t i = ((size_t)blockIdx.x * blockDim.x + threadIdx.x) * 4;
    size_t t = i >> 12;
    size_t h = i & (HIDDEN - 1);
    const float4 a = *(const float4*)(g_scratch + ((t << 1) + 0) * HIDDEN + h);
    const float4 b = *(const float4*)(g_scratch + ((t << 1) + 1) * HIDDEN + h);
    float4 o;
    o.x = a.x + b.x; o.y = a.y + b.y; o.z = a.z + b.z; o.w = a.w + b.w;
    *(float4*)(out + i) = o;
}

// ---------------- kernel 4: l_bal scalar ----------------
__global__ __launch_bounds__(256) void lbal_kernel(float* __restrict__ out)
{
    int warp = threadIdx.x >> 5;
    int lane = threadIdx.x & 31;
    float s = 0.f;
    for (int t = lane; t < T_TOK; t += 32) s += g_probs[t * N_EXP + warp];
    #pragma unroll
    for (int o = 16; o > 0; o >>= 1) s += __shfl_xor_sync(0xffffffffu, s, o);
    __shared__ float P[N_EXP];
    if (lane == 0) P[warp] = s;
    __syncthreads();
    if (threadIdx.x == 0) {
        float l = 0.f;
        #pragma unroll
        for (int e = 0; e < N_EXP; e++) {
            float f = (float)g_count[e] / (float)T_TOK;
            l += f * (P[e] / (float)T_TOK);
        }
        out[(size_t)T_TOK * HIDDEN] = (float)N_EXP * l;
    }
}

// ---------------- launch ----------------
extern "C" void kernel_launch(void* const* d_in, const int* in_sizes, int n_in,
                              void* d_out, int out_size)
{
    const float* x  = (const float*)d_in[0];   // [1,2048,1024]
    const float* rw = (const float*)d_in[1];   // [8,1024]
    const float* w1 = (const float*)d_in[2];   // [8,4096,1024]
    const float* b1 = (const float*)d_in[3];   // [8,4096]
    float* out = (float*)d_out;

    const int smem_dyn = 4 * TILE_FLOATS * 4;  // 2 bufs x (A+B) x 18KB = 73728 B
    cudaFuncSetAttribute(moe_gemm_mma, cudaFuncAttributeMaxDynamicSharedMemorySize, smem_dyn);

    init_kernel<<<1, 32>>>();
    router_kernel<<<T_TOK, 256>>>(x, rw);

    dim3 gemm_grid(T_TOK / BM, HIDDEN / BN, N_EXP);   // (16 mtiles, 32 ntiles, 8 experts)
    moe_gemm_mma<<<gemm_grid, 128, smem_dyn>>>(x, w1, b1);

    size_t total = (size_t)T_TOK * HIDDEN;
    combine_kernel<<<(unsigned)(total / 4 / 256), 256>>>(out);

    if ((size_t)out_size > total) {
        lbal_kernel<<<1, 256>>>(out);
    }
}

// round 5
// speedup vs baseline: 4.9071x; 1.3682x over previous
#include <cuda_runtime.h>
#include <cuda_fp16.h>
#include <cuda_bf16.h>
#include <math_constants.h>
#include <cstdint>

// Problem constants
#define T_TOK   2048
#define D_MODEL 1024
#define HIDDEN  4096
#define N_EXP   8
// TOP_K = 2

// GEMM tiling (fp16 path)
#define BM 128
#define BN 128
#define BK 64                       // fp16 elems per k-chunk => 128B rows
#define NCH (D_MODEL / BK)          // 16
#define TILE_B 16384                // 128 rows x 128 bytes per operand buffer

// ---------------- device scratch (allocation-free) ----------------
__device__ int    g_count[N_EXP];
__device__ int    g_tok[N_EXP * T_TOK];              // packed token*2 + slot
__device__ float  g_wt [N_EXP * T_TOK];
__device__ float  g_probs[T_TOK * N_EXP];
__device__ float  g_scratch[(size_t)T_TOK * 2 * HIDDEN]; // 64 MB per-(token,slot) partials
__device__ __half g_w1h[(size_t)N_EXP * HIDDEN * D_MODEL]; // 64 MB fp16 weights
__device__ __half g_xh [(size_t)T_TOK * D_MODEL];          // 4 MB fp16 activations

// ---------------- helpers ----------------
__device__ __forceinline__ uint32_t smem_u32(const void* p) {
    uint32_t a;
    asm("{ .reg .u64 t; cvta.to.shared.u64 t, %1; cvt.u32.u64 %0, t; }" : "=r"(a) : "l"(p));
    return a;
}

__device__ __forceinline__ void cp16(uint32_t dst, const void* src, int sz) {
    asm volatile("cp.async.cg.shared.global [%0], [%1], 16, %2;"
                 :: "r"(dst), "l"(src), "r"(sz) : "memory");
}

#define LDSM4(r, addr) \
    asm volatile("ldmatrix.sync.aligned.m8n8.x4.shared.b16 {%0,%1,%2,%3}, [%4];" \
                 : "=r"((r)[0]), "=r"((r)[1]), "=r"((r)[2]), "=r"((r)[3]) : "r"(addr))

__device__ __forceinline__ void mma_f16(float* d, const uint32_t* a, const uint32_t* b) {
    asm volatile(
        "mma.sync.aligned.m16n8k16.row.col.f32.f16.f16.f32 "
        "{%0,%1,%2,%3}, {%4,%5,%6,%7}, {%8,%9}, {%0,%1,%2,%3};"
        : "+f"(d[0]), "+f"(d[1]), "+f"(d[2]), "+f"(d[3])
        : "r"(a[0]), "r"(a[1]), "r"(a[2]), "r"(a[3]), "r"(b[0]), "r"(b[1]));
}

// ---------------- kernel 0: zero counters ----------------
__global__ void init_kernel() {
    if (threadIdx.x < N_EXP) g_count[threadIdx.x] = 0;
}

// ---------------- conversion kernels (fp32 -> fp16) ----------------
__global__ __launch_bounds__(256) void convert_w1_kernel(const float* __restrict__ w1) {
    size_t i = ((size_t)blockIdx.x * 256 + threadIdx.x) * 8;
    float4 f0 = *(const float4*)(w1 + i);
    float4 f1 = *(const float4*)(w1 + i + 4);
    union { __half2 h[4]; uint4 u; } p;
    p.h[0] = __floats2half2_rn(f0.x, f0.y);
    p.h[1] = __floats2half2_rn(f0.z, f0.w);
    p.h[2] = __floats2half2_rn(f1.x, f1.y);
    p.h[3] = __floats2half2_rn(f1.z, f1.w);
    *(uint4*)(g_w1h + i) = p.u;
}

__global__ __launch_bounds__(256) void convert_x_kernel(const float* __restrict__ x) {
    size_t i = ((size_t)blockIdx.x * 256 + threadIdx.x) * 8;
    float4 f0 = *(const float4*)(x + i);
    float4 f1 = *(const float4*)(x + i + 4);
    union { __half2 h[4]; uint4 u; } p;
    p.h[0] = __floats2half2_rn(f0.x, f0.y);
    p.h[1] = __floats2half2_rn(f0.z, f0.w);
    p.h[2] = __floats2half2_rn(f1.x, f1.y);
    p.h[3] = __floats2half2_rn(f1.z, f1.w);
    *(uint4*)(g_xh + i) = p.u;
}

// ---------------- kernel 1: router ----------------
__global__ __launch_bounds__(256) void router_kernel(
    const float* __restrict__ x, const float* __restrict__ rw)
{
    int t    = blockIdx.x;
    int warp = threadIdx.x >> 5;
    int lane = threadIdx.x & 31;

    const float4* xv = (const float4*)(x + (size_t)t * D_MODEL);
    const float4* wv = (const float4*)(rw + (size_t)warp * D_MODEL);
    float s = 0.f;
    #pragma unroll
    for (int i = 0; i < 8; i++) {
        float4 a = xv[lane + i * 32];
        float4 b = wv[lane + i * 32];
        s += a.x * b.x + a.y * b.y + a.z * b.z + a.w * b.w;
    }
    #pragma unroll
    for (int o = 16; o > 0; o >>= 1) s += __shfl_xor_sync(0xffffffffu, s, o);

    __shared__ float logits[N_EXP];
    if (lane == 0) logits[warp] = s;
    __syncthreads();

    if (threadIdx.x == 0) {
        int e0 = 0; float v0 = logits[0];
        #pragma unroll
        for (int e = 1; e < N_EXP; e++) if (logits[e] > v0) { v0 = logits[e]; e0 = e; }
        int e1 = -1; float v1 = -CUDART_INF_F;
        #pragma unroll
        for (int e = 0; e < N_EXP; e++) if (e != e0 && logits[e] > v1) { v1 = logits[e]; e1 = e; }

        float ex1 = expf(v1 - v0);
        float inv = 1.0f / (1.0f + ex1);
        float c0 = inv, c1 = ex1 * inv;

        int p0 = atomicAdd(&g_count[e0], 1);
        g_tok[e0 * T_TOK + p0] = t * 2 + 0;
        g_wt [e0 * T_TOK + p0] = c0;
        int p1 = atomicAdd(&g_count[e1], 1);
        g_tok[e1 * T_TOK + p1] = t * 2 + 1;
        g_wt [e1 * T_TOK + p1] = c1;

        float mx = v0;
        float pe[N_EXP], se = 0.f;
        #pragma unroll
        for (int e = 0; e < N_EXP; e++) { pe[e] = expf(logits[e] - mx); se += pe[e]; }
        float invs = 1.0f / se;
        #pragma unroll
        for (int e = 0; e < N_EXP; e++) g_probs[t * N_EXP + e] = pe[e] * invs;
    }
}

// ---------------- kernel 2: fp16 m16n8k16 grouped expert GEMM ----------------
// CTA 128x128, 8 warps (2x4), warp tile 64x32. A rows gathered via router lists.
// fp16 operands staged with cp.async into XOR-swizzled 128B rows; ldmatrix.x4
// fragment loads; fp32 accumulate.
__global__ void __launch_bounds__(256, 1) moe_gemm_h(const float* __restrict__ b1)
{
    const int e   = blockIdx.z;
    const int cnt = g_count[e];
    const int m0  = blockIdx.x * BM;
    if (m0 >= cnt) return;
    const int n0  = blockIdx.y * BN;

    extern __shared__ __half hsm[];
    const uint32_t uS = smem_u32(hsm);
    // layout: A0 | A1 | B0 | B1, each TILE_B bytes

    __shared__ int   s_tok[BM];
    __shared__ float s_w[BM];
    __shared__ float s_bias[BN];

    const int tid = threadIdx.x;
    const int wid = tid >> 5;
    const int lid = tid & 31;
    const int wm  = (wid >> 2) * 64;    // warp row base (0 or 64)
    const int wn  = (wid & 3) * 32;     // warp col base (0/32/64/96)

    if (tid < BM) {
        int r = m0 + tid;
        if (r < cnt) { s_tok[tid] = g_tok[e * T_TOK + r]; s_w[tid] = g_wt[e * T_TOK + r]; }
        else         { s_tok[tid] = -1;                   s_w[tid] = 0.f; }
    } else {
        int j = tid - 128;
        s_bias[j] = b1[(size_t)e * HIDDEN + n0 + j];
    }
    __syncthreads();

    const __half* w1base = g_w1h + ((size_t)e * HIDDEN + n0) * D_MODEL;

    // staging: 128 rows x 8 chunks of 16B per operand; 4 A + 4 B cp.async/thread
    auto stage = [&](int buf, int k0) {
        const uint32_t ab = uS + (uint32_t)buf * TILE_B;
        const uint32_t bb = uS + 2 * TILE_B + (uint32_t)buf * TILE_B;
        #pragma unroll
        for (int i = 0; i < 4; i++) {
            int idx = tid + i * 256;          // 0..1023
            int row = idx >> 3;
            int ch  = idx & 7;
            uint32_t soff = (uint32_t)(row * 128 + ((ch ^ (row & 7)) << 4));

            int pk  = s_tok[row];
            int tok = pk >= 0 ? (pk >> 1) : 0;
            cp16(ab + soff, g_xh + (size_t)tok * D_MODEL + k0 + ch * 8, pk >= 0 ? 16 : 0);
            cp16(bb + soff, w1base + (size_t)row * D_MODEL + k0 + ch * 8, 16);
        }
        asm volatile("cp.async.commit_group;" ::: "memory");
    };

    float acc[4][4][4];
    #pragma unroll
    for (int mt = 0; mt < 4; mt++)
        #pragma unroll
        for (int nt = 0; nt < 4; nt++)
            #pragma unroll
            for (int q = 0; q < 4; q++) acc[mt][nt][q] = 0.f;

    stage(0, 0);

    // ldmatrix lane mapping precompute
    const int l8   = lid & 7;            // row within 8x8 tile
    const int jA_m = ((lid >> 3) & 1) * 8;   // A tile m offset
    const int jA_k = (lid >> 4) & 1;         // A tile k-chunk offset
    const int jB_n = ((lid >> 4) & 1) * 8;   // B tile n offset
    const int jB_k = (lid >> 3) & 1;         // B tile k-chunk offset

    for (int c = 0; c < NCH; ++c) {
        if (c + 1 < NCH) stage((c + 1) & 1, (c + 1) * BK);
        else asm volatile("cp.async.commit_group;" ::: "memory");
        asm volatile("cp.async.wait_group 1;" ::: "memory");
        __syncthreads();

        const uint32_t ab = uS + (uint32_t)(c & 1) * TILE_B;
        const uint32_t bb = uS + 2 * TILE_B + (uint32_t)(c & 1) * TILE_B;

        #pragma unroll
        for (int s = 0; s < 4; s++) {          // 4 k16 steps per chunk
            uint32_t a[4][4];
            #pragma unroll
            for (int mt = 0; mt < 4; mt++) {
                int row = wm + mt * 16 + jA_m + l8;
                int ch  = 2 * s + jA_k;
                LDSM4(a[mt], ab + (uint32_t)(row * 128 + ((ch ^ (row & 7)) << 4)));
            }
            #pragma unroll
            for (int g = 0; g < 2; g++) {      // two n16 groups
                uint32_t b[4];
                int row = wn + g * 16 + jB_n + l8;
                int ch  = 2 * s + jB_k;
                LDSM4(b, bb + (uint32_t)(row * 128 + ((ch ^ (row & 7)) << 4)));
                #pragma unroll
                for (int mt = 0; mt < 4; mt++) {
                    mma_f16(acc[mt][2 * g + 0], a[mt], b + 0);
                    mma_f16(acc[mt][2 * g + 1], a[mt], b + 2);
                }
            }
        }
        __syncthreads();
    }

    // ---- epilogue: scale + bias, scatter to per-(token,slot) scratch ----
    const int lr = lid >> 2;
    const int lc = lid & 3;
    #pragma unroll
    for (int mt = 0; mt < 4; mt++) {
        int r_lo = wm + mt * 16 + lr;
        int r_hi = r_lo + 8;
        if ((m0 + r_lo) < cnt) {
            int   pk = s_tok[r_lo];
            float wt = s_w[r_lo];
            float* dst = g_scratch + (size_t)pk * HIDDEN + n0;
            #pragma unroll
            for (int nt = 0; nt < 4; nt++) {
                int col = wn + nt * 8 + lc * 2;
                float2 v;
                v.x = wt * (acc[mt][nt][0] + s_bias[col]);
                v.y = wt * (acc[mt][nt][1] + s_bias[col + 1]);
                *(float2*)(dst + col) = v;
            }
        }
        if ((m0 + r_hi) < cnt) {
            int   pk = s_tok[r_hi];
            float wt = s_w[r_hi];
            float* dst = g_scratch + (size_t)pk * HIDDEN + n0;
            #pragma unroll
            for (int nt = 0; nt < 4; nt++) {
                int col = wn + nt * 8 + lc * 2;
                float2 v;
                v.x = wt * (acc[mt][nt][2] + s_bias[col]);
                v.y = wt * (acc[mt][nt][3] + s_bias[col + 1]);
                *(float2*)(dst + col) = v;
            }
        }
    }
}

// ---------------- kernel 3: combine two slots ----------------
__global__ __launch_bounds__(256) void combine_kernel(float* __restrict__ out)
{
    size_t i = ((size_t)blockIdx.x * blockDim.x + threadIdx.x) * 4;
    size_t t = i >> 12;
    size_t h = i & (HIDDEN - 1);
    const float4 a = *(const float4*)(g_scratch + ((t << 1) + 0) * HIDDEN + h);
    const float4 b = *(const float4*)(g_scratch + ((t << 1) + 1) * HIDDEN + h);
    float4 o;
    o.x = a.x + b.x; o.y = a.y + b.y; o.z = a.z + b.z; o.w = a.w + b.w;
    *(float4*)(out + i) = o;
}

// ---------------- kernel 4: l_bal scalar ----------------
__global__ __launch_bounds__(256) void lbal_kernel(float* __restrict__ out)
{
    int warp = threadIdx.x >> 5;
    int lane = threadIdx.x & 31;
    float s = 0.f;
    for (int t = lane; t < T_TOK; t += 32) s += g_probs[t * N_EXP + warp];
    #pragma unroll
    for (int o = 16; o > 0; o >>= 1) s += __shfl_xor_sync(0xffffffffu, s, o);
    __shared__ float P[N_EXP];
    if (lane == 0) P[warp] = s;
    __syncthreads();
    if (threadIdx.x == 0) {
        float l = 0.f;
        #pragma unroll
        for (int e = 0; e < N_EXP; e++) {
            float f = (float)g_count[e] / (float)T_TOK;
            l += f * (P[e] / (float)T_TOK);
        }
        out[(size_t)T_TOK * HIDDEN] = (float)N_EXP * l;
    }
}

// ---------------- launch ----------------
extern "C" void kernel_launch(void* const* d_in, const int* in_sizes, int n_in,
                              void* d_out, int out_size)
{
    const float* x  = (const float*)d_in[0];   // [1,2048,1024]
    const float* rw = (const float*)d_in[1];   // [8,1024]
    const float* w1 = (const float*)d_in[2];   // [8,4096,1024]
    const float* b1 = (const float*)d_in[3];   // [8,4096]
    float* out = (float*)d_out;

    const int smem_dyn = 4 * TILE_B;   // 64 KB
    cudaFuncSetAttribute(moe_gemm_h, cudaFuncAttributeMaxDynamicSharedMemorySize, smem_dyn);

    init_kernel<<<1, 32>>>();
    convert_x_kernel<<<(T_TOK * D_MODEL) / (256 * 8), 256>>>(x);
    convert_w1_kernel<<<(N_EXP * HIDDEN * D_MODEL) / (256 * 8), 256>>>(w1);
    router_kernel<<<T_TOK, 256>>>(x, rw);

    dim3 gemm_grid(T_TOK / BM, HIDDEN / BN, N_EXP);   // (16 mtiles, 32 ntiles, 8 experts)
    moe_gemm_h<<<gemm_grid, 256, smem_dyn>>>(b1);

    size_t total = (size_t)T_TOK * HIDDEN;
    combine_kernel<<<(unsigned)(total / 4 / 256), 256>>>(out);

    if ((size_t)out_size > total) {
        lbal_kernel<<<1, 256>>>(out);
    }
}

// round 6
// speedup vs baseline: 6.3682x; 1.2977x over previous
#include <cuda_runtime.h>
#include <cuda_fp16.h>
#include <cuda_bf16.h>
#include <math_constants.h>
#include <cstdint>

// Problem constants
#define T_TOK   2048
#define D_MODEL 1024
#define HIDDEN  4096
#define N_EXP   8
// TOP_K = 2

// GEMM tiling (fp16 path): CTA 128x128, 4 warps (2x2), warp tile 64x64
#define BM 128
#define BN 128
#define BK 64                       // fp16 elems per k-chunk => 128B rows
#define NCH (D_MODEL / BK)          // 16
#define TILE_B 16384                // 128 rows x 128 bytes per operand buffer
#define STAGES 3

// ---------------- device scratch (allocation-free) ----------------
__device__ int    g_count[N_EXP];
__device__ int    g_tok[N_EXP * T_TOK];              // packed token*2 + slot
__device__ float  g_wt [N_EXP * T_TOK];
__device__ float  g_probs[T_TOK * N_EXP];
__device__ __half g_w1h[(size_t)N_EXP * HIDDEN * D_MODEL]; // 64 MB fp16 weights
__device__ __half g_xh [(size_t)T_TOK * D_MODEL];          // 4 MB fp16 activations

// ---------------- helpers ----------------
__device__ __forceinline__ uint32_t smem_u32(const void* p) {
    uint32_t a;
    asm("{ .reg .u64 t; cvta.to.shared.u64 t, %1; cvt.u32.u64 %0, t; }" : "=r"(a) : "l"(p));
    return a;
}

__device__ __forceinline__ void cp16(uint32_t dst, const void* src, int sz) {
    asm volatile("cp.async.cg.shared.global [%0], [%1], 16, %2;"
                 :: "r"(dst), "l"(src), "r"(sz) : "memory");
}

#define LDSM4(r, addr) \
    asm volatile("ldmatrix.sync.aligned.m8n8.x4.shared.b16 {%0,%1,%2,%3}, [%4];" \
                 : "=r"((r)[0]), "=r"((r)[1]), "=r"((r)[2]), "=r"((r)[3]) : "r"(addr))

__device__ __forceinline__ void mma_f16(float* d, const uint32_t* a, const uint32_t* b) {
    asm volatile(
        "mma.sync.aligned.m16n8k16.row.col.f32.f16.f16.f32 "
        "{%0,%1,%2,%3}, {%4,%5,%6,%7}, {%8,%9}, {%0,%1,%2,%3};"
        : "+f"(d[0]), "+f"(d[1]), "+f"(d[2]), "+f"(d[3])
        : "r"(a[0]), "r"(a[1]), "r"(a[2]), "r"(a[3]), "r"(b[0]), "r"(b[1]));
}

// ---------------- kernel 0: zero counters ----------------
__global__ void init_kernel() {
    if (threadIdx.x < N_EXP) g_count[threadIdx.x] = 0;
}

// ---------------- kernel: zero the output ----------------
__global__ __launch_bounds__(256) void zero_out_kernel(float* __restrict__ out) {
    size_t i = ((size_t)blockIdx.x * 256 + threadIdx.x) * 4;
    *(float4*)(out + i) = make_float4(0.f, 0.f, 0.f, 0.f);
}

// ---------------- conversion kernel (w1 fp32 -> fp16) ----------------
__global__ __launch_bounds__(256) void convert_w1_kernel(const float* __restrict__ w1) {
    size_t i = ((size_t)blockIdx.x * 256 + threadIdx.x) * 8;
    float4 f0 = *(const float4*)(w1 + i);
    float4 f1 = *(const float4*)(w1 + i + 4);
    union { __half2 h[4]; uint4 u; } p;
    p.h[0] = __floats2half2_rn(f0.x, f0.y);
    p.h[1] = __floats2half2_rn(f0.z, f0.w);
    p.h[2] = __floats2half2_rn(f1.x, f1.y);
    p.h[3] = __floats2half2_rn(f1.z, f1.w);
    *(uint4*)(g_w1h + i) = p.u;
}

// ---------------- kernel 1: router (+ fused x -> fp16 conversion) ----------------
__global__ __launch_bounds__(256) void router_kernel(
    const float* __restrict__ x, const float* __restrict__ rw)
{
    int t    = blockIdx.x;
    int warp = threadIdx.x >> 5;
    int lane = threadIdx.x & 31;

    const float4* xv = (const float4*)(x + (size_t)t * D_MODEL);
    const float4* wv = (const float4*)(rw + (size_t)warp * D_MODEL);
    float s = 0.f;
    #pragma unroll
    for (int i = 0; i < 8; i++) {
        float4 a = xv[lane + i * 32];
        float4 b = wv[lane + i * 32];
        s += a.x * b.x + a.y * b.y + a.z * b.z + a.w * b.w;
        if (warp == 0) {   // warp 0 sees the full row: convert to fp16 once
            __half2 h0 = __floats2half2_rn(a.x, a.y);
            __half2 h1 = __floats2half2_rn(a.z, a.w);
            *(__half2*)(g_xh + (size_t)t * D_MODEL + (lane + i * 32) * 4)     = h0;
            *(__half2*)(g_xh + (size_t)t * D_MODEL + (lane + i * 32) * 4 + 2) = h1;
        }
    }
    #pragma unroll
    for (int o = 16; o > 0; o >>= 1) s += __shfl_xor_sync(0xffffffffu, s, o);

    __shared__ float logits[N_EXP];
    if (lane == 0) logits[warp] = s;
    __syncthreads();

    if (threadIdx.x == 0) {
        int e0 = 0; float v0 = logits[0];
        #pragma unroll
        for (int e = 1; e < N_EXP; e++) if (logits[e] > v0) { v0 = logits[e]; e0 = e; }
        int e1 = -1; float v1 = -CUDART_INF_F;
        #pragma unroll
        for (int e = 0; e < N_EXP; e++) if (e != e0 && logits[e] > v1) { v1 = logits[e]; e1 = e; }

        float ex1 = expf(v1 - v0);
        float inv = 1.0f / (1.0f + ex1);
        float c0 = inv, c1 = ex1 * inv;

        int p0 = atomicAdd(&g_count[e0], 1);
        g_tok[e0 * T_TOK + p0] = t * 2 + 0;
        g_wt [e0 * T_TOK + p0] = c0;
        int p1 = atomicAdd(&g_count[e1], 1);
        g_tok[e1 * T_TOK + p1] = t * 2 + 1;
        g_wt [e1 * T_TOK + p1] = c1;

        float mx = v0;
        float pe[N_EXP], se = 0.f;
        #pragma unroll
        for (int e = 0; e < N_EXP; e++) { pe[e] = expf(logits[e] - mx); se += pe[e]; }
        float invs = 1.0f / se;
        #pragma unroll
        for (int e = 0; e < N_EXP; e++) g_probs[t * N_EXP + e] = pe[e] * invs;
    }
}

// ---------------- kernel 2: fp16 m16n8k16 grouped expert GEMM ----------------
// CTA 128x128, 4 warps (2x2), warp tile 64x64. A rows gathered via router lists.
// 3-stage cp.async pipeline, XOR-swizzled 128B rows, ldmatrix.x4, fp32 accumulate.
// Epilogue: wt*(acc+bias) atomicAdd'ed directly into the zeroed output (each
// element receives exactly 2 contributions -> order-independent, deterministic).
__global__ void __launch_bounds__(128, 2) moe_gemm_h(
    const float* __restrict__ b1, float* __restrict__ out)
{
    const int e   = blockIdx.z;
    const int cnt = g_count[e];
    const int m0  = blockIdx.x * BM;
    if (m0 >= cnt) return;
    const int n0  = blockIdx.y * BN;

    extern __shared__ __half hsm[];
    const uint32_t uS = smem_u32(hsm);
    // layout: A0 | B0 | A1 | B1 | A2 | B2, each TILE_B bytes

    __shared__ int   s_tok[BM];
    __shared__ float s_w[BM];
    __shared__ float s_bias[BN];

    const int tid = threadIdx.x;
    const int wid = tid >> 5;
    const int lid = tid & 31;
    const int wm  = (wid >> 1) * 64;    // warp row base (0 or 64)
    const int wn  = (wid & 1) * 64;     // warp col base (0 or 64)

    {
        int r = m0 + tid;
        if (r < cnt) { s_tok[tid] = g_tok[e * T_TOK + r]; s_w[tid] = g_wt[e * T_TOK + r]; }
        else         { s_tok[tid] = -1;                   s_w[tid] = 0.f; }
        s_bias[tid] = b1[(size_t)e * HIDDEN + n0 + tid];
    }
    __syncthreads();

    const __half* w1base = g_w1h + ((size_t)e * HIDDEN + n0) * D_MODEL;

    // staging: 128 rows x 8 chunks of 16B per operand; 8 A + 8 B cp.async/thread
    auto stage = [&](int buf, int k0) {
        const uint32_t ab = uS + (uint32_t)buf * 2 * TILE_B;
        const uint32_t bb = ab + TILE_B;
        #pragma unroll
        for (int i = 0; i < 8; i++) {
            int idx = tid + i * 128;          // 0..1023
            int row = idx >> 3;
            int ch  = idx & 7;
            uint32_t soff = (uint32_t)(row * 128 + ((ch ^ (row & 7)) << 4));

            int pk  = s_tok[row];
            int tok = pk >= 0 ? (pk >> 1) : 0;
            cp16(ab + soff, g_xh + (size_t)tok * D_MODEL + k0 + ch * 8, pk >= 0 ? 16 : 0);
            cp16(bb + soff, w1base + (size_t)row * D_MODEL + k0 + ch * 8, 16);
        }
        asm volatile("cp.async.commit_group;" ::: "memory");
    };

    float acc[4][8][4];
    #pragma unroll
    for (int mt = 0; mt < 4; mt++)
        #pragma unroll
        for (int nt = 0; nt < 8; nt++)
            #pragma unroll
            for (int q = 0; q < 4; q++) acc[mt][nt][q] = 0.f;

    stage(0, 0);
    stage(1, BK);

    // ldmatrix lane mapping
    const int l8   = lid & 7;
    const int jA_m = ((lid >> 3) & 1) * 8;
    const int jA_k = (lid >> 4) & 1;
    const int jB_n = ((lid >> 4) & 1) * 8;
    const int jB_k = (lid >> 3) & 1;

    for (int c = 0; c < NCH; ++c) {
        if (c + 2 < NCH) stage((c + 2) % STAGES, (c + 2) * BK);
        else asm volatile("cp.async.commit_group;" ::: "memory");
        asm volatile("cp.async.wait_group 2;" ::: "memory");
        __syncthreads();

        const uint32_t ab = uS + (uint32_t)(c % STAGES) * 2 * TILE_B;
        const uint32_t bb = ab + TILE_B;

        #pragma unroll
        for (int s = 0; s < 4; s++) {          // 4 k16 steps per chunk
            uint32_t a[4][4];
            #pragma unroll
            for (int mt = 0; mt < 4; mt++) {
                int row = wm + mt * 16 + jA_m + l8;
                int ch  = 2 * s + jA_k;
                LDSM4(a[mt], ab + (uint32_t)(row * 128 + ((ch ^ (row & 7)) << 4)));
            }
            uint32_t b[4][4];
            #pragma unroll
            for (int bg = 0; bg < 4; bg++) {   // four n16 groups
                int row = wn + bg * 16 + jB_n + l8;
                int ch  = 2 * s + jB_k;
                LDSM4(b[bg], bb + (uint32_t)(row * 128 + ((ch ^ (row & 7)) << 4)));
            }
            #pragma unroll
            for (int mt = 0; mt < 4; mt++)
                #pragma unroll
                for (int bg = 0; bg < 4; bg++) {
                    mma_f16(acc[mt][2 * bg + 0], a[mt], b[bg] + 0);
                    mma_f16(acc[mt][2 * bg + 1], a[mt], b[bg] + 2);
                }
        }
        __syncthreads();
    }

    // ---- epilogue: wt*(acc+bias) atomically accumulated into out ----
    const int lr = lid >> 2;
    const int lc = lid & 3;
    #pragma unroll
    for (int mt = 0; mt < 4; mt++) {
        int r_lo = wm + mt * 16 + lr;
        int r_hi = r_lo + 8;
        if ((m0 + r_lo) < cnt) {
            int   tok = s_tok[r_lo] >> 1;
            float wt  = s_w[r_lo];
            float* dst = out + (size_t)tok * HIDDEN + n0;
            #pragma unroll
            for (int nt = 0; nt < 8; nt++) {
                int col = wn + nt * 8 + lc * 2;
                atomicAdd(dst + col,     wt * (acc[mt][nt][0] + s_bias[col]));
                atomicAdd(dst + col + 1, wt * (acc[mt][nt][1] + s_bias[col + 1]));
            }
        }
        if ((m0 + r_hi) < cnt) {
            int   tok = s_tok[r_hi] >> 1;
            float wt  = s_w[r_hi];
            float* dst = out + (size_t)tok * HIDDEN + n0;
            #pragma unroll
            for (int nt = 0; nt < 8; nt++) {
                int col = wn + nt * 8 + lc * 2;
                atomicAdd(dst + col,     wt * (acc[mt][nt][2] + s_bias[col]));
                atomicAdd(dst + col + 1, wt * (acc[mt][nt][3] + s_bias[col + 1]));
            }
        }
    }
}

// ---------------- kernel 4: l_bal scalar ----------------
__global__ __launch_bounds__(256) void lbal_kernel(float* __restrict__ out)
{
    int warp = threadIdx.x >> 5;
    int lane = threadIdx.x & 31;
    float s = 0.f;
    for (int t = lane; t < T_TOK; t += 32) s += g_probs[t * N_EXP + warp];
    #pragma unroll
    for (int o = 16; o > 0; o >>= 1) s += __shfl_xor_sync(0xffffffffu, s, o);
    __shared__ float P[N_EXP];
    if (lane == 0) P[warp] = s;
    __syncthreads();
    if (threadIdx.x == 0) {
        float l = 0.f;
        #pragma unroll
        for (int e = 0; e < N_EXP; e++) {
            float f = (float)g_count[e] / (float)T_TOK;
            l += f * (P[e] / (float)T_TOK);
        }
        out[(size_t)T_TOK * HIDDEN] = (float)N_EXP * l;
    }
}

// ---------------- launch ----------------
extern "C" void kernel_launch(void* const* d_in, const int* in_sizes, int n_in,
                              void* d_out, int out_size)
{
    const float* x  = (const float*)d_in[0];   // [1,2048,1024]
    const float* rw = (const float*)d_in[1];   // [8,1024]
    const float* w1 = (const float*)d_in[2];   // [8,4096,1024]
    const float* b1 = (const float*)d_in[3];   // [8,4096]
    float* out = (float*)d_out;

    const int smem_dyn = STAGES * 2 * TILE_B;   // 96 KB
    cudaFuncSetAttribute(moe_gemm_h, cudaFuncAttributeMaxDynamicSharedMemorySize, smem_dyn);

    init_kernel<<<1, 32>>>();
    router_kernel<<<T_TOK, 256>>>(x, rw);
    convert_w1_kernel<<<(N_EXP * HIDDEN * D_MODEL) / (256 * 8), 256>>>(w1);

    size_t total = (size_t)T_TOK * HIDDEN;
    zero_out_kernel<<<(unsigned)(total / 4 / 256), 256>>>(out);

    dim3 gemm_grid(T_TOK / BM, HIDDEN / BN, N_EXP);   // (16 mtiles, 32 ntiles, 8 experts)
    moe_gemm_h<<<gemm_grid, 128, smem_dyn>>>(b1, out);

    if ((size_t)out_size > total) {
        lbal_kernel<<<1, 256>>>(out);
    }
}

// round 7
// speedup vs baseline: 6.6271x; 1.0406x over previous
#include <cuda_runtime.h>
#include <cuda_fp16.h>
#include <cuda_bf16.h>
#include <math_constants.h>
#include <cstdint>

// Problem constants
#define T_TOK   2048
#define D_MODEL 1024
#define HIDDEN  4096
#define N_EXP   8
// TOP_K = 2

// GEMM tiling (fp16 path): CTA 128x128, 4 warps (2x2), warp tile 64x64
#define BM 128
#define BN 128
#define BK 64                       // fp16 elems per k-chunk => 128B rows
#define NCH (D_MODEL / BK)          // 16
#define TILE_B 16384                // 128 rows x 128 bytes per operand buffer
#define STAGES 3

// ---------------- device scratch (allocation-free) ----------------
__device__ int    g_count[N_EXP];
__device__ int    g_tok[N_EXP * T_TOK];              // packed token*2 + slot
__device__ float  g_wt [N_EXP * T_TOK];
__device__ float  g_probs[T_TOK * N_EXP];
__device__ __half g_w1h[(size_t)N_EXP * HIDDEN * D_MODEL]; // 64 MB fp16 weights
__device__ __half g_xh [(size_t)T_TOK * D_MODEL];          // 4 MB fp16 activations

// ---------------- helpers ----------------
__device__ __forceinline__ uint32_t smem_u32(const void* p) {
    uint32_t a;
    asm("{ .reg .u64 t; cvta.to.shared.u64 t, %1; cvt.u32.u64 %0, t; }" : "=r"(a) : "l"(p));
    return a;
}

__device__ __forceinline__ void cp16(uint32_t dst, const void* src, int sz) {
    asm volatile("cp.async.cg.shared.global [%0], [%1], 16, %2;"
                 :: "r"(dst), "l"(src), "r"(sz) : "memory");
}

#define LDSM4(r, addr) \
    asm volatile("ldmatrix.sync.aligned.m8n8.x4.shared.b16 {%0,%1,%2,%3}, [%4];" \
                 : "=r"((r)[0]), "=r"((r)[1]), "=r"((r)[2]), "=r"((r)[3]) : "r"(addr))

__device__ __forceinline__ void mma_f16(float* d, const uint32_t* a, const uint32_t* b) {
    asm volatile(
        "mma.sync.aligned.m16n8k16.row.col.f32.f16.f16.f32 "
        "{%0,%1,%2,%3}, {%4,%5,%6,%7}, {%8,%9}, {%0,%1,%2,%3};"
        : "+f"(d[0]), "+f"(d[1]), "+f"(d[2]), "+f"(d[3])
        : "r"(a[0]), "r"(a[1]), "r"(a[2]), "r"(a[3]), "r"(b[0]), "r"(b[1]));
}

// ---------------- kernel 0: zero counters ----------------
__global__ void init_kernel() {
    if (threadIdx.x < N_EXP) g_count[threadIdx.x] = 0;
}

// ---------------- conversion kernel (w1 fp32 -> fp16) ----------------
__global__ __launch_bounds__(256) void convert_w1_kernel(const float* __restrict__ w1) {
    size_t i = ((size_t)blockIdx.x * 256 + threadIdx.x) * 8;
    float4 f0 = *(const float4*)(w1 + i);
    float4 f1 = *(const float4*)(w1 + i + 4);
    union { __half2 h[4]; uint4 u; } p;
    p.h[0] = __floats2half2_rn(f0.x, f0.y);
    p.h[1] = __floats2half2_rn(f0.z, f0.w);
    p.h[2] = __floats2half2_rn(f1.x, f1.y);
    p.h[3] = __floats2half2_rn(f1.z, f1.w);
    *(uint4*)(g_w1h + i) = p.u;
}

// ---------------- kernel 1: router (+ fused x -> fp16 conversion) ----------------
__global__ __launch_bounds__(256) void router_kernel(
    const float* __restrict__ x, const float* __restrict__ rw)
{
    int t    = blockIdx.x;
    int warp = threadIdx.x >> 5;
    int lane = threadIdx.x & 31;

    const float4* xv = (const float4*)(x + (size_t)t * D_MODEL);
    const float4* wv = (const float4*)(rw + (size_t)warp * D_MODEL);
    float s = 0.f;
    #pragma unroll
    for (int i = 0; i < 8; i++) {
        float4 a = xv[lane + i * 32];
        float4 b = wv[lane + i * 32];
        s += a.x * b.x + a.y * b.y + a.z * b.z + a.w * b.w;
        if (warp == 0) {   // warp 0 sees the full row: convert to fp16 once
            __half2 h0 = __floats2half2_rn(a.x, a.y);
            __half2 h1 = __floats2half2_rn(a.z, a.w);
            *(__half2*)(g_xh + (size_t)t * D_MODEL + (lane + i * 32) * 4)     = h0;
            *(__half2*)(g_xh + (size_t)t * D_MODEL + (lane + i * 32) * 4 + 2) = h1;
        }
    }
    #pragma unroll
    for (int o = 16; o > 0; o >>= 1) s += __shfl_xor_sync(0xffffffffu, s, o);

    __shared__ float logits[N_EXP];
    if (lane == 0) logits[warp] = s;
    __syncthreads();

    if (threadIdx.x == 0) {
        int e0 = 0; float v0 = logits[0];
        #pragma unroll
        for (int e = 1; e < N_EXP; e++) if (logits[e] > v0) { v0 = logits[e]; e0 = e; }
        int e1 = -1; float v1 = -CUDART_INF_F;
        #pragma unroll
        for (int e = 0; e < N_EXP; e++) if (e != e0 && logits[e] > v1) { v1 = logits[e]; e1 = e; }

        float ex1 = expf(v1 - v0);
        float inv = 1.0f / (1.0f + ex1);
        float c0 = inv, c1 = ex1 * inv;

        int p0 = atomicAdd(&g_count[e0], 1);
        g_tok[e0 * T_TOK + p0] = t * 2 + 0;
        g_wt [e0 * T_TOK + p0] = c0;
        int p1 = atomicAdd(&g_count[e1], 1);
        g_tok[e1 * T_TOK + p1] = t * 2 + 1;
        g_wt [e1 * T_TOK + p1] = c1;

        float mx = v0;
        float pe[N_EXP], se = 0.f;
        #pragma unroll
        for (int e = 0; e < N_EXP; e++) { pe[e] = expf(logits[e] - mx); se += pe[e]; }
        float invs = 1.0f / se;
        #pragma unroll
        for (int e = 0; e < N_EXP; e++) g_probs[t * N_EXP + e] = pe[e] * invs;
    }
}

// ---------------- kernel 2: fp16 m16n8k16 grouped expert GEMM ----------------
// CTA 128x128, 4 warps (2x2), warp tile 64x64. A rows gathered via router lists.
// 3-stage cp.async pipeline, XOR-swizzled 128B rows, ldmatrix.x4, fp32 accumulate.
// Epilogue: wt*(acc+bias) atomicAdd'ed into zeroed output (exactly 2 contributions
// per element -> order-independent, deterministic).
__global__ void __launch_bounds__(128, 2) moe_gemm_h(
    const float* __restrict__ b1, float* __restrict__ out)
{
    const int e   = blockIdx.z;
    const int cnt = g_count[e];
    const int m0  = blockIdx.x * BM;
    if (m0 >= cnt) return;
    const int n0  = blockIdx.y * BN;

    extern __shared__ __half hsm[];
    const uint32_t uS = smem_u32(hsm);

    __shared__ int   s_tok[BM];
    __shared__ float s_w[BM];
    __shared__ float s_bias[BN];

    const int tid = threadIdx.x;
    const int wid = tid >> 5;
    const int lid = tid & 31;
    const int wm  = (wid >> 1) * 64;
    const int wn  = (wid & 1) * 64;

    {
        int r = m0 + tid;
        if (r < cnt) { s_tok[tid] = g_tok[e * T_TOK + r]; s_w[tid] = g_wt[e * T_TOK + r]; }
        else         { s_tok[tid] = -1;                   s_w[tid] = 0.f; }
        s_bias[tid] = b1[(size_t)e * HIDDEN + n0 + tid];
    }
    __syncthreads();

    const __half* w1base = g_w1h + ((size_t)e * HIDDEN + n0) * D_MODEL;

    auto stage = [&](int buf, int k0) {
        const uint32_t ab = uS + (uint32_t)buf * 2 * TILE_B;
        const uint32_t bb = ab + TILE_B;
        #pragma unroll
        for (int i = 0; i < 8; i++) {
            int idx = tid + i * 128;
            int row = idx >> 3;
            int ch  = idx & 7;
            uint32_t soff = (uint32_t)(row * 128 + ((ch ^ (row & 7)) << 4));

            int pk  = s_tok[row];
            int tok = pk >= 0 ? (pk >> 1) : 0;
            cp16(ab + soff, g_xh + (size_t)tok * D_MODEL + k0 + ch * 8, pk >= 0 ? 16 : 0);
            cp16(bb + soff, w1base + (size_t)row * D_MODEL + k0 + ch * 8, 16);
        }
        asm volatile("cp.async.commit_group;" ::: "memory");
    };

    float acc[4][8][4];
    #pragma unroll
    for (int mt = 0; mt < 4; mt++)
        #pragma unroll
        for (int nt = 0; nt < 8; nt++)
            #pragma unroll
            for (int q = 0; q < 4; q++) acc[mt][nt][q] = 0.f;

    stage(0, 0);
    stage(1, BK);

    const int l8   = lid & 7;
    const int jA_m = ((lid >> 3) & 1) * 8;
    const int jA_k = (lid >> 4) & 1;
    const int jB_n = ((lid >> 4) & 1) * 8;
    const int jB_k = (lid >> 3) & 1;

    for (int c = 0; c < NCH; ++c) {
        if (c + 2 < NCH) stage((c + 2) % STAGES, (c + 2) * BK);
        else asm volatile("cp.async.commit_group;" ::: "memory");
        asm volatile("cp.async.wait_group 2;" ::: "memory");
        __syncthreads();

        const uint32_t ab = uS + (uint32_t)(c % STAGES) * 2 * TILE_B;
        const uint32_t bb = ab + TILE_B;

        #pragma unroll
        for (int s = 0; s < 4; s++) {
            uint32_t a[4][4];
            #pragma unroll
            for (int mt = 0; mt < 4; mt++) {
                int row = wm + mt * 16 + jA_m + l8;
                int ch  = 2 * s + jA_k;
                LDSM4(a[mt], ab + (uint32_t)(row * 128 + ((ch ^ (row & 7)) << 4)));
            }
            uint32_t b[4][4];
            #pragma unroll
            for (int bg = 0; bg < 4; bg++) {
                int row = wn + bg * 16 + jB_n + l8;
                int ch  = 2 * s + jB_k;
                LDSM4(b[bg], bb + (uint32_t)(row * 128 + ((ch ^ (row & 7)) << 4)));
            }
            #pragma unroll
            for (int mt = 0; mt < 4; mt++)
                #pragma unroll
                for (int bg = 0; bg < 4; bg++) {
                    mma_f16(acc[mt][2 * bg + 0], a[mt], b[bg] + 0);
                    mma_f16(acc[mt][2 * bg + 1], a[mt], b[bg] + 2);
                }
        }
        __syncthreads();
    }

    const int lr = lid >> 2;
    const int lc = lid & 3;
    #pragma unroll
    for (int mt = 0; mt < 4; mt++) {
        int r_lo = wm + mt * 16 + lr;
        int r_hi = r_lo + 8;
        if ((m0 + r_lo) < cnt) {
            int   tok = s_tok[r_lo] >> 1;
            float wt  = s_w[r_lo];
            float* dst = out + (size_t)tok * HIDDEN + n0;
            #pragma unroll
            for (int nt = 0; nt < 8; nt++) {
                int col = wn + nt * 8 + lc * 2;
                atomicAdd(dst + col,     wt * (acc[mt][nt][0] + s_bias[col]));
                atomicAdd(dst + col + 1, wt * (acc[mt][nt][1] + s_bias[col + 1]));
            }
        }
        if ((m0 + r_hi) < cnt) {
            int   tok = s_tok[r_hi] >> 1;
            float wt  = s_w[r_hi];
            float* dst = out + (size_t)tok * HIDDEN + n0;
            #pragma unroll
            for (int nt = 0; nt < 8; nt++) {
                int col = wn + nt * 8 + lc * 2;
                atomicAdd(dst + col,     wt * (acc[mt][nt][2] + s_bias[col]));
                atomicAdd(dst + col + 1, wt * (acc[mt][nt][3] + s_bias[col + 1]));
            }
        }
    }
}

// ---------------- kernel 4: l_bal scalar ----------------
__global__ __launch_bounds__(256) void lbal_kernel(float* __restrict__ out)
{
    int warp = threadIdx.x >> 5;
    int lane = threadIdx.x & 31;
    float s = 0.f;
    for (int t = lane; t < T_TOK; t += 32) s += g_probs[t * N_EXP + warp];
    #pragma unroll
    for (int o = 16; o > 0; o >>= 1) s += __shfl_xor_sync(0xffffffffu, s, o);
    __shared__ float P[N_EXP];
    if (lane == 0) P[warp] = s;
    __syncthreads();
    if (threadIdx.x == 0) {
        float l = 0.f;
        #pragma unroll
        for (int e = 0; e < N_EXP; e++) {
            float f = (float)g_count[e] / (float)T_TOK;
            l += f * (P[e] / (float)T_TOK);
        }
        out[(size_t)T_TOK * HIDDEN] = (float)N_EXP * l;
    }
}

// ---------------- launch: fork independent pre-work across streams ----------------
extern "C" void kernel_launch(void* const* d_in, const int* in_sizes, int n_in,
                              void* d_out, int out_size)
{
    const float* x  = (const float*)d_in[0];   // [1,2048,1024]
    const float* rw = (const float*)d_in[1];   // [8,1024]
    const float* w1 = (const float*)d_in[2];   // [8,4096,1024]
    const float* b1 = (const float*)d_in[3];   // [8,4096]
    float* out = (float*)d_out;

    // Host-side objects created once; graph capture records only the topology.
    static cudaStream_t s1 = nullptr, s2 = nullptr;
    static cudaEvent_t evr = nullptr, ev1 = nullptr, ev2 = nullptr;
    static bool smem_set = false;
    if (!s1) {
        cudaStreamCreateWithFlags(&s1, cudaStreamNonBlocking);
        cudaStreamCreateWithFlags(&s2, cudaStreamNonBlocking);
        cudaEventCreateWithFlags(&evr, cudaEventDisableTiming);
        cudaEventCreateWithFlags(&ev1, cudaEventDisableTiming);
        cudaEventCreateWithFlags(&ev2, cudaEventDisableTiming);
    }
    if (!smem_set) {
        cudaFuncSetAttribute(moe_gemm_h, cudaFuncAttributeMaxDynamicSharedMemorySize,
                             STAGES * 2 * TILE_B);
        smem_set = true;
    }

    size_t total = (size_t)T_TOK * HIDDEN;

    // root work on the capture (default) stream
    init_kernel<<<1, 32>>>();
    cudaEventRecord(evr, 0);

    // fork: router (+x convert) on s1, weight conversion on s2, out-zeroing on 0
    cudaStreamWaitEvent(s1, evr, 0);
    cudaStreamWaitEvent(s2, evr, 0);
    router_kernel<<<T_TOK, 256, 0, s1>>>(x, rw);
    convert_w1_kernel<<<(N_EXP * HIDDEN * D_MODEL) / (256 * 8), 256, 0, s2>>>(w1);
    cudaMemsetAsync(out, 0, total * sizeof(float), 0);

    // join
    cudaEventRecord(ev1, s1);
    cudaEventRecord(ev2, s2);
    cudaStreamWaitEvent(0, ev1, 0);
    cudaStreamWaitEvent(0, ev2, 0);

    dim3 gemm_grid(T_TOK / BM, HIDDEN / BN, N_EXP);   // (16 mtiles, 32 ntiles, 8 experts)
    moe_gemm_h<<<gemm_grid, 128, STAGES * 2 * TILE_B>>>(b1, out);

    if ((size_t)out_size > total) {
        lbal_kernel<<<1, 256>>>(out);
    }
}

// round 10
// speedup vs baseline: 6.6866x; 1.0090x over previous
#include <cuda_runtime.h>
#include <cuda_fp16.h>
#include <cuda_bf16.h>
#include <math_constants.h>
#include <cstdint>

// Problem constants
#define T_TOK   2048
#define D_MODEL 1024
#define HIDDEN  4096
#define N_EXP   8
// TOP_K = 2

// GEMM tiling (fp16 path): CTA 128x128, 4 warps (2x2), warp tile 64x64
#define BM 128
#define BN 128
#define BK 64                       // fp16 elems per k-chunk => 128B rows
#define NCH (D_MODEL / BK)          // 16
#define TILE_B 16384                // 128 rows x 128 bytes per operand buffer
#define STAGES 3

// prep-kernel grid partition
#define NB_ROUTER 2048                                  // one block per token
#define NB_CONV   ((N_EXP * HIDDEN * D_MODEL) / (256 * 8))   // 4096
#define NB_ZERO   ((T_TOK * HIDDEN) / (256 * 4))             // 8192
#define NB_PREP   (NB_ROUTER + NB_CONV + NB_ZERO)            // 14336

// ---------------- device scratch (allocation-free) ----------------
__device__ int    g_count[N_EXP];
__device__ int    g_tok[N_EXP * T_TOK];              // packed token*2 + slot
__device__ float  g_wt [N_EXP * T_TOK];
__device__ float  g_probs[T_TOK * N_EXP];
__device__ __half g_w1h[(size_t)N_EXP * HIDDEN * D_MODEL]; // 64 MB fp16 weights
__device__ __half g_xh [(size_t)T_TOK * D_MODEL];          // 4 MB fp16 activations

// ---------------- helpers ----------------
__device__ __forceinline__ uint32_t smem_u32(const void* p) {
    uint32_t a;
    asm("{ .reg .u64 t; cvta.to.shared.u64 t, %1; cvt.u32.u64 %0, t; }" : "=r"(a) : "l"(p));
    return a;
}

__device__ __forceinline__ void cp16(uint32_t dst, const void* src, int sz) {
    asm volatile("cp.async.cg.shared.global [%0], [%1], 16, %2;"
                 :: "r"(dst), "l"(src), "r"(sz) : "memory");
}

#define LDSM4(r, addr) \
    asm volatile("ldmatrix.sync.aligned.m8n8.x4.shared.b16 {%0,%1,%2,%3}, [%4];" \
                 : "=r"((r)[0]), "=r"((r)[1]), "=r"((r)[2]), "=r"((r)[3]) : "r"(addr))

__device__ __forceinline__ void mma_f16(float* d, const uint32_t* a, const uint32_t* b) {
    asm volatile(
        "mma.sync.aligned.m16n8k16.row.col.f32.f16.f16.f32 "
        "{%0,%1,%2,%3}, {%4,%5,%6,%7}, {%8,%9}, {%0,%1,%2,%3};"
        : "+f"(d[0]), "+f"(d[1]), "+f"(d[2]), "+f"(d[3])
        : "r"(a[0]), "r"(a[1]), "r"(a[2]), "r"(a[3]), "r"(b[0]), "r"(b[1]));
}

// ---------------- kernel 0: zero counters ----------------
__global__ void init_kernel() {
    if (threadIdx.x < N_EXP) g_count[threadIdx.x] = 0;
}

// ---------------- kernel 1: fused prep ----------------
// Grid partition (no streams needed — one launch overlaps all independent work):
//   blocks [0, 2048)            : router for token b (+ fused x->fp16 by warp 0)
//   blocks [2048, 2048+4096)    : w1 fp32->fp16 conversion
//   blocks [6144, 6144+8192)    : zero the output buffer
__global__ __launch_bounds__(256) void prep_kernel(
    const float* __restrict__ x, const float* __restrict__ rw,
    const float* __restrict__ w1, float* __restrict__ out)
{
    const int b = blockIdx.x;

    if (b >= NB_ROUTER + NB_CONV) {            // ---- zero-out branch ----
        size_t i = ((size_t)(b - NB_ROUTER - NB_CONV) * 256 + threadIdx.x) * 4;
        *(float4*)(out + i) = make_float4(0.f, 0.f, 0.f, 0.f);
        return;
    }

    if (b >= NB_ROUTER) {                      // ---- w1 conversion branch ----
        size_t i = ((size_t)(b - NB_ROUTER) * 256 + threadIdx.x) * 8;
        float4 f0 = *(const float4*)(w1 + i);
        float4 f1 = *(const float4*)(w1 + i + 4);
        union { __half2 h[4]; uint4 u; } p;
        p.h[0] = __floats2half2_rn(f0.x, f0.y);
        p.h[1] = __floats2half2_rn(f0.z, f0.w);
        p.h[2] = __floats2half2_rn(f1.x, f1.y);
        p.h[3] = __floats2half2_rn(f1.z, f1.w);
        *(uint4*)(g_w1h + i) = p.u;
        return;
    }

    // ---- router branch ----
    int t    = b;
    int warp = threadIdx.x >> 5;
    int lane = threadIdx.x & 31;

    const float4* xv = (const float4*)(x + (size_t)t * D_MODEL);
    const float4* wv = (const float4*)(rw + (size_t)warp * D_MODEL);
    float s = 0.f;
    #pragma unroll
    for (int i = 0; i < 8; i++) {
        float4 a = xv[lane + i * 32];
        float4 w = wv[lane + i * 32];
        s += a.x * w.x + a.y * w.y + a.z * w.z + a.w * w.w;
        if (warp == 0) {   // warp 0 sees the full row: convert x to fp16 once
            __half2 h0 = __floats2half2_rn(a.x, a.y);
            __half2 h1 = __floats2half2_rn(a.z, a.w);
            *(__half2*)(g_xh + (size_t)t * D_MODEL + (lane + i * 32) * 4)     = h0;
            *(__half2*)(g_xh + (size_t)t * D_MODEL + (lane + i * 32) * 4 + 2) = h1;
        }
    }
    #pragma unroll
    for (int o = 16; o > 0; o >>= 1) s += __shfl_xor_sync(0xffffffffu, s, o);

    __shared__ float logits[N_EXP];
    if (lane == 0) logits[warp] = s;
    __syncthreads();

    if (threadIdx.x == 0) {
        int e0 = 0; float v0 = logits[0];
        #pragma unroll
        for (int e = 1; e < N_EXP; e++) if (logits[e] > v0) { v0 = logits[e]; e0 = e; }
        int e1 = -1; float v1 = -CUDART_INF_F;
        #pragma unroll
        for (int e = 0; e < N_EXP; e++) if (e != e0 && logits[e] > v1) { v1 = logits[e]; e1 = e; }

        float ex1 = expf(v1 - v0);
        float inv = 1.0f / (1.0f + ex1);
        float c0 = inv, c1 = ex1 * inv;

        int p0 = atomicAdd(&g_count[e0], 1);
        g_tok[e0 * T_TOK + p0] = t * 2 + 0;
        g_wt [e0 * T_TOK + p0] = c0;
        int p1 = atomicAdd(&g_count[e1], 1);
        g_tok[e1 * T_TOK + p1] = t * 2 + 1;
        g_wt [e1 * T_TOK + p1] = c1;

        float mx = v0;
        float pe[N_EXP], se = 0.f;
        #pragma unroll
        for (int e = 0; e < N_EXP; e++) { pe[e] = expf(logits[e] - mx); se += pe[e]; }
        float invs = 1.0f / se;
        #pragma unroll
        for (int e = 0; e < N_EXP; e++) g_probs[t * N_EXP + e] = pe[e] * invs;
    }
}

// ---------------- kernel 2: fp16 m16n8k16 grouped expert GEMM ----------------
// CTA 128x128, 4 warps (2x2), warp tile 64x64. A rows gathered via router lists.
// 3-stage cp.async pipeline with a SINGLE __syncthreads per chunk:
//   wait_group 1  -> group c retired (two groups always in flight via empty commits)
//   sync          -> also proves all warps finished reading buffer (c+2)%3 == (c-1)%3
//   stage(c+2)    -> safe overwrite; async copy overlaps compute(c)
//   compute(c)
// Epilogue: wt*(acc+bias) atomicAdd'ed into zeroed output (exactly 2 contributions
// per element -> order-independent, deterministic).
__global__ void __launch_bounds__(128, 2) moe_gemm_h(
    const float* __restrict__ b1, float* __restrict__ out)
{
    const int e   = blockIdx.z;
    const int cnt = g_count[e];
    const int m0  = blockIdx.x * BM;
    if (m0 >= cnt) return;
    const int n0  = blockIdx.y * BN;

    extern __shared__ __half hsm[];
    const uint32_t uS = smem_u32(hsm);

    __shared__ int   s_tok[BM];
    __shared__ float s_w[BM];
    __shared__ float s_bias[BN];

    const int tid = threadIdx.x;
    const int wid = tid >> 5;
    const int lid = tid & 31;
    const int wm  = (wid >> 1) * 64;
    const int wn  = (wid & 1) * 64;

    {
        int r = m0 + tid;
        if (r < cnt) { s_tok[tid] = g_tok[e * T_TOK + r]; s_w[tid] = g_wt[e * T_TOK + r]; }
        else         { s_tok[tid] = -1;                   s_w[tid] = 0.f; }
        s_bias[tid] = b1[(size_t)e * HIDDEN + n0 + tid];
    }
    __syncthreads();

    const __half* w1base = g_w1h + ((size_t)e * HIDDEN + n0) * D_MODEL;

    auto stage = [&](int buf, int k0) {
        const uint32_t ab = uS + (uint32_t)buf * 2 * TILE_B;
        const uint32_t bb = ab + TILE_B;
        #pragma unroll
        for (int i = 0; i < 8; i++) {
            int idx = tid + i * 128;
            int row = idx >> 3;
            int ch  = idx & 7;
            uint32_t soff = (uint32_t)(row * 128 + ((ch ^ (row & 7)) << 4));

            int pk  = s_tok[row];
            int tok = pk >= 0 ? (pk >> 1) : 0;
            cp16(ab + soff, g_xh + (size_t)tok * D_MODEL + k0 + ch * 8, pk >= 0 ? 16 : 0);
            cp16(bb + soff, w1base + (size_t)row * D_MODEL + k0 + ch * 8, 16);
        }
        asm volatile("cp.async.commit_group;" ::: "memory");
    };

    float acc[4][8][4];
    #pragma unroll
    for (int mt = 0; mt < 4; mt++)
        #pragma unroll
        for (int nt = 0; nt < 8; nt++)
            #pragma unroll
            for (int q = 0; q < 4; q++) acc[mt][nt][q] = 0.f;

    stage(0, 0);
    stage(1, BK);

    const int l8   = lid & 7;
    const int jA_m = ((lid >> 3) & 1) * 8;
    const int jA_k = (lid >> 4) & 1;
    const int jB_n = ((lid >> 4) & 1) * 8;
    const int jB_k = (lid >> 3) & 1;

    for (int c = 0; c < NCH; ++c) {
        asm volatile("cp.async.wait_group 1;" ::: "memory");
        __syncthreads();

        if (c + 2 < NCH) stage((c + 2) % STAGES, (c + 2) * BK);
        else asm volatile("cp.async.commit_group;" ::: "memory");  // keep 2 groups in flight

        const uint32_t ab = uS + (uint32_t)(c % STAGES) * 2 * TILE_B;
        const uint32_t bb = ab + TILE_B;

        #pragma unroll
        for (int s = 0; s < 4; s++) {
            uint32_t a[4][4];
            #pragma unroll
            for (int mt = 0; mt < 4; mt++) {
                int row = wm + mt * 16 + jA_m + l8;
                int ch  = 2 * s + jA_k;
                LDSM4(a[mt], ab + (uint32_t)(row * 128 + ((ch ^ (row & 7)) << 4)));
            }
            uint32_t b[4][4];
            #pragma unroll
            for (int bg = 0; bg < 4; bg++) {
                int row = wn + bg * 16 + jB_n + l8;
                int ch  = 2 * s + jB_k;
                LDSM4(b[bg], bb + (uint32_t)(row * 128 + ((ch ^ (row & 7)) << 4)));
            }
            #pragma unroll
            for (int mt = 0; mt < 4; mt++)
                #pragma unroll
                for (int bg = 0; bg < 4; bg++) {
                    mma_f16(acc[mt][2 * bg + 0], a[mt], b[bg] + 0);
                    mma_f16(acc[mt][2 * bg + 1], a[mt], b[bg] + 2);
                }
        }
    }

    const int lr = lid >> 2;
    const int lc = lid & 3;
    #pragma unroll
    for (int mt = 0; mt < 4; mt++) {
        int r_lo = wm + mt * 16 + lr;
        int r_hi = r_lo + 8;
        if ((m0 + r_lo) < cnt) {
            int   tok = s_tok[r_lo] >> 1;
            float wt  = s_w[r_lo];
            float* dst = out + (size_t)tok * HIDDEN + n0;
            #pragma unroll
            for (int nt = 0; nt < 8; nt++) {
                int col = wn + nt * 8 + lc * 2;
                atomicAdd(dst + col,     wt * (acc[mt][nt][0] + s_bias[col]));
                atomicAdd(dst + col + 1, wt * (acc[mt][nt][1] + s_bias[col + 1]));
            }
        }
        if ((m0 + r_hi) < cnt) {
            int   tok = s_tok[r_hi] >> 1;
            float wt  = s_w[r_hi];
            float* dst = out + (size_t)tok * HIDDEN + n0;
            #pragma unroll
            for (int nt = 0; nt < 8; nt++) {
                int col = wn + nt * 8 + lc * 2;
                atomicAdd(dst + col,     wt * (acc[mt][nt][2] + s_bias[col]));
                atomicAdd(dst + col + 1, wt * (acc[mt][nt][3] + s_bias[col + 1]));
            }
        }
    }
}

// ---------------- kernel 4: l_bal scalar ----------------
__global__ __launch_bounds__(256) void lbal_kernel(float* __restrict__ out)
{
    int warp = threadIdx.x >> 5;
    int lane = threadIdx.x & 31;
    float s = 0.f;
    for (int t = lane; t < T_TOK; t += 32) s += g_probs[t * N_EXP + warp];
    #pragma unroll
    for (int o = 16; o > 0; o >>= 1) s += __shfl_xor_sync(0xffffffffu, s, o);
    __shared__ float P[N_EXP];
    if (lane == 0) P[warp] = s;
    __syncthreads();
    if (threadIdx.x == 0) {
        float l = 0.f;
        #pragma unroll
        for (int e = 0; e < N_EXP; e++) {
            float f = (float)g_count[e] / (float)T_TOK;
            l += f * (P[e] / (float)T_TOK);
        }
        out[(size_t)T_TOK * HIDDEN] = (float)N_EXP * l;
    }
}

// ---------------- launch: simple linear chain, zero stream/event objects ----------
extern "C" void kernel_launch(void* const* d_in, const int* in_sizes, int n_in,
                              void* d_out, int out_size)
{
    const float* x  = (const float*)d_in[0];   // [1,2048,1024]
    const float* rw = (const float*)d_in[1];   // [8,1024]
    const float* w1 = (const float*)d_in[2];   // [8,4096,1024]
    const float* b1 = (const float*)d_in[3];   // [8,4096]
    float* out = (float*)d_out;

    static bool smem_set = false;
    if (!smem_set) {
        cudaFuncSetAttribute(moe_gemm_h, cudaFuncAttributeMaxDynamicSharedMemorySize,
                             STAGES * 2 * TILE_B);
        smem_set = true;
    }

    init_kernel<<<1, 32>>>();
    prep_kernel<<<NB_PREP, 256>>>(x, rw, w1, out);

    dim3 gemm_grid(T_TOK / BM, HIDDEN / BN, N_EXP);   // (16 mtiles, 32 ntiles, 8 experts)
    moe_gemm_h<<<gemm_grid, 128, STAGES * 2 * TILE_B>>>(b1, out);

    size_t total = (size_t)T_TOK * HIDDEN;
    if ((size_t)out_size > total) {
        lbal_kernel<<<1, 256>>>(out);
    }
}